// round 2
// baseline (speedup 1.0000x reference)
#include <cuda_runtime.h>
#include <cstdint>

#define EPS 1e-10f
#define P_NODES (1u << 20)        // nodes per tree (H*W = 1024*1024)
#define KN 4096                   // nodes per CTA
#define THREADS 256
#define NPT (KN / THREADS)        // 16 nodes per thread
#define MAX_TREES 4

// Per-node (value, epoch) publication word. 8B aligned -> single-word atomic st/ld.
__device__ unsigned long long g_scratch[(size_t)MAX_TREES * P_NODES];
__device__ unsigned int g_epoch = 0;
__device__ unsigned int g_ticket = 0;

__global__ void mt_init_kernel() {
    if (threadIdx.x == 0) { g_epoch++; g_ticket = 0; }
}

__global__ __launch_bounds__(THREADS, 3)
void mt_main_kernel(const float* __restrict__ x,
                    const float* __restrict__ weight,   // (N,17,1)
                    const float* __restrict__ bias,     // (N,1)
                    const float* __restrict__ attrs,    // (T,P,15)
                    const int*   __restrict__ parents,  // (T,P)
                    float* __restrict__ out,            // (T,P)
                    int n_trees, int N)
{
    __shared__ float stage[THREADS * 15];
    __shared__ int s_vb;

    if (threadIdx.x == 0) s_vb = atomicAdd(&g_ticket, 1u);
    __syncthreads();
    const int vb   = s_vb;
    const int tree = vb % n_trees;          // round-robin trees so all chains ripple concurrently
    const int lb   = vb / n_trees;          // block index within tree (increasing node ranges)
    const unsigned int epoch = g_epoch;     // set by init kernel in a prior launch (L1 flushed per launch)

    const size_t tb = (size_t)tree * P_NODES;
    const float* xt = x + tb;
    const float* at = attrs + tb * 15;
    const int*   pt = parents + tb;
    float*       ot = out + tb;
    unsigned long long* sc = g_scratch + tb;

    const int n = tree % N;                 // tree t = b*N + n
    float wv[17];
    #pragma unroll
    for (int i = 0; i < 17; i++) wv[i] = __ldg(&weight[n * 17 + i]);
    const float bv = __ldg(&bias[n]);

    const int base = lb * KN;               // tree-local first node of this CTA

    float contrib[NPT];
    int   par[NPT];

    // ---------------- Phase A: contrib for 16 chunks of 256 nodes ----------------
    for (int j = 0; j < NPT; j++) {
        const int chunk = base + j * THREADS;
        const float* ap = at + (size_t)chunk * 15;

        __syncthreads();                    // protect prior iteration's stage reads
        #pragma unroll
        for (int i = 0; i < 15; i++)
            stage[i * THREADS + threadIdx.x] = __ldg(&ap[i * THREADS + threadIdx.x]);
        __syncthreads();

        const float* a = &stage[threadIdx.x * 15];   // stride 15: bank-conflict-free
        // feats: a0..a4 | log(|a6..a14|+eps) | sqrt(a7)/(sqrt(a6)+eps) | cos(a5) | sin(a5)
        float lin = bv;
        lin += a[0]*wv[0] + a[1]*wv[1] + a[2]*wv[2] + a[3]*wv[3] + a[4]*wv[4];
        #pragma unroll
        for (int c = 0; c < 9; c++)
            lin += __logf(fabsf(a[6 + c]) + EPS) * wv[5 + c];
        lin += __fdividef(__fsqrt_rn(a[7]), __fsqrt_rn(a[6]) + EPS) * wv[14];
        float sa, ca;
        __sincosf(a[5], &sa, &ca);
        lin += ca * wv[15] + sa * wv[16];
        const float score = __fdividef(1.0f, 1.0f + __expf(-lin));

        const int node = chunk + threadIdx.x;
        const int p    = __ldg(&pt[node]);
        const float xv = __ldg(&xt[node]);
        const float diff = (p == node) ? xv : (xv - __ldcg(&xt[p]));  // .cg: no L1 pollution on random gather
        contrib[j] = diff * score;
        par[j]     = p;
    }

    // ---------------- Phase B: resolve recurrence out[p] = contrib[p] + out[par[p]] ----------------
    // Each thread's nodes are strictly increasing (j*256 + tid), so self-deps are already published.
    #pragma unroll 1
    for (int j = 0; j < NPT; j++) {
        const int node = base + j * THREADS + threadIdx.x;
        const int p    = par[j];
        float val;
        if (p == node) {
            val = contrib[j];               // root
        } else {
            unsigned long long got = __ldcg(&sc[p]);
            while ((unsigned int)(got >> 32) != epoch) {
                __nanosleep(40);
                got = __ldcg(&sc[p]);
            }
            val = contrib[j] + __uint_as_float((unsigned int)got);
        }
        const unsigned long long packed =
            ((unsigned long long)epoch << 32) | (unsigned long long)__float_as_uint(val);
        __stcg(&sc[node], packed);          // publish: tag+value in one 8B word, no fence needed
        ot[node] = val;                     // coalesced final store
    }
}

extern "C" void kernel_launch(void* const* d_in, const int* in_sizes, int n_in,
                              void* d_out, int out_size)
{
    const float* x       = (const float*)d_in[0];   // (B,N,H,W) f32
    const float* weight  = (const float*)d_in[1];   // (N,17,1)  f32
    const float* bias    = (const float*)d_in[2];   // (N,1)     f32
    const float* attrs   = (const float*)d_in[3];   // (B,N,P,15) f32
    const int*   parents = (const int*)d_in[4];     // (B,N,P)   i32

    const int n_trees = in_sizes[0] / (int)P_NODES; // B*N
    const int N       = in_sizes[1] / 17;

    mt_init_kernel<<<1, 32>>>();
    const int grid = n_trees * ((int)P_NODES / KN); // 1024 CTAs
    mt_main_kernel<<<grid, THREADS>>>(x, weight, bias, attrs, parents,
                                      (float*)d_out, n_trees, N);
}

// round 3
// speedup vs baseline: 2.7148x; 2.7148x over previous
#include <cuda_runtime.h>
#include <cstdint>

#define EPS 1e-10f
#define P_NODES (1u << 20)        // nodes per tree (H*W)
#define KN 8192                   // nodes per CTA
#define THREADS 256
#define NPT (KN / THREADS)        // 32 nodes per thread (bitmask-tracked)
#define MAX_TREES 4

// Per-node (value, epoch) publication word: 8B single-word L2 atomicity.
__device__ unsigned long long g_scratch[(size_t)MAX_TREES * P_NODES];
__device__ float              g_contrib[(size_t)MAX_TREES * P_NODES];
__device__ unsigned int g_epoch = 0;
__device__ unsigned int g_ticket = 0;

__global__ void mt_init_kernel() {
    if (threadIdx.x == 0) { g_epoch++; g_ticket = 0; }
}

__global__ __launch_bounds__(THREADS, 4)
void mt_main_kernel(const float* __restrict__ x,
                    const float* __restrict__ weight,   // (N,17,1)
                    const float* __restrict__ bias,     // (N,1)
                    const float* __restrict__ attrs,    // (T,P,15)
                    const int*   __restrict__ parents,  // (T,P)
                    float* __restrict__ out,            // (T,P)
                    int n_trees, int N)
{
    __shared__ float stage[THREADS * 15];   // 15 KB
    __shared__ int   spar[KN];              // 32 KB
    __shared__ int   s_vb;

    if (threadIdx.x == 0) s_vb = atomicAdd(&g_ticket, 1u);
    __syncthreads();
    const int vb   = s_vb;
    const int tree = vb % n_trees;          // interleave trees: all 4 ripples run concurrently
    const int lb   = vb / n_trees;
    const unsigned int epoch = g_epoch;

    const size_t tb = (size_t)tree * P_NODES;
    const float* xt = x + tb;
    const float* at = attrs + tb * 15;
    const int*   pt = parents + tb;
    float*       ot = out + tb;
    unsigned long long* sc = g_scratch + tb;
    float*              ct = g_contrib + tb;

    const int n = tree % N;
    float wv[17];
    #pragma unroll
    for (int i = 0; i < 17; i++) wv[i] = __ldg(&weight[n * 17 + i]);
    const float bv = __ldg(&bias[n]);

    const int base = lb * KN;

    // ---------------- Phase A: contrib for 32 chunks of 256 nodes ----------------
    for (int j = 0; j < NPT; j++) {
        const int chunk = base + j * THREADS;
        const float* ap = at + (size_t)chunk * 15;

        __syncthreads();
        #pragma unroll
        for (int i = 0; i < 15; i++)
            stage[i * THREADS + threadIdx.x] = __ldg(&ap[i * THREADS + threadIdx.x]);
        __syncthreads();

        const float* a = &stage[threadIdx.x * 15];
        float lin = bv;
        lin += a[0]*wv[0] + a[1]*wv[1] + a[2]*wv[2] + a[3]*wv[3] + a[4]*wv[4];
        #pragma unroll
        for (int c = 0; c < 9; c++)
            lin += __logf(fabsf(a[6 + c]) + EPS) * wv[5 + c];
        lin += __fdividef(__fsqrt_rn(a[7]), __fsqrt_rn(a[6]) + EPS) * wv[14];
        float sa, ca;
        __sincosf(a[5], &sa, &ca);
        lin += ca * wv[15] + sa * wv[16];
        const float score = __fdividef(1.0f, 1.0f + __expf(-lin));

        const int node = chunk + threadIdx.x;
        const int p    = __ldg(&pt[node]);
        const float xv = __ldg(&xt[node]);
        const float diff = (p == node) ? xv : (xv - __ldcg(&xt[p]));
        __stcg(&ct[node], diff * score);    // contrib lives in L2
        spar[j * THREADS + threadIdx.x] = p;
    }

    // ---------------- Phase B: out-of-order ripple ----------------
    // Resolve any pending node whose parent is already published; no intra-thread
    // ordering constraint, so the critical path collapses to tree depth.
    unsigned int pending = 0xFFFFFFFFu;     // NPT == 32 bits
    while (pending) {
        unsigned int rem = pending;
        bool progress = false;
        while (rem) {
            const int j = __ffs(rem) - 1;
            rem &= rem - 1;
            const int sidx = j * THREADS + threadIdx.x;
            const int node = base + sidx;
            const int p    = spar[sidx];
            float val;
            if (p == node) {
                val = __ldcg(&ct[node]);    // root
            } else {
                const unsigned long long got = __ldcg(&sc[p]);
                if ((unsigned int)(got >> 32) != epoch) continue;   // parent not ready
                val = __ldcg(&ct[node]) + __uint_as_float((unsigned int)got);
            }
            __stcg(&sc[node],
                   ((unsigned long long)epoch << 32) | (unsigned long long)__float_as_uint(val));
            ot[node] = val;
            pending &= ~(1u << j);
            progress = true;
        }
        if (pending && !progress) __nanosleep(64);
    }
}

extern "C" void kernel_launch(void* const* d_in, const int* in_sizes, int n_in,
                              void* d_out, int out_size)
{
    const float* x       = (const float*)d_in[0];   // (B,N,H,W) f32
    const float* weight  = (const float*)d_in[1];   // (N,17,1)  f32
    const float* bias    = (const float*)d_in[2];   // (N,1)     f32
    const float* attrs   = (const float*)d_in[3];   // (B,N,P,15) f32
    const int*   parents = (const int*)d_in[4];     // (B,N,P)   i32

    const int n_trees = in_sizes[0] / (int)P_NODES; // B*N = 4
    const int N       = in_sizes[1] / 17;

    mt_init_kernel<<<1, 32>>>();
    const int grid = n_trees * ((int)P_NODES / KN); // 512 CTAs -> single wave
    mt_main_kernel<<<grid, THREADS>>>(x, weight, bias, attrs, parents,
                                      (float*)d_out, n_trees, N);
}

// round 5
// speedup vs baseline: 7.3590x; 2.7107x over previous
#include <cuda_runtime.h>
#include <cstdint>

#define EPS 1e-10f
#define P_NODES (1u << 20)          // nodes per tree (H*W)
#define THREADS 256
#define MAX_TREES 4
#define T0 2048                     // resolved by K2 (in-block doubling)
#define T1 131072                   // resolved by K3 (walk to <T0)

// Per-node record written once by K1, read-only afterwards:
//   .x = __float_as_uint(contrib), .y = parent index
__device__ uint2 g_rec[(size_t)MAX_TREES * P_NODES];

// ---------------------------------------------------------------------------
// K1: contrib[i] = (x[i] - x[parent[i]]) * sigmoid(w . feats(attrs[i]) + b)
// Pure streaming pass; packs (contrib, parent) records.
// ---------------------------------------------------------------------------
__global__ __launch_bounds__(THREADS)
void k1_contrib(const float* __restrict__ x,
                const float* __restrict__ weight,   // (N,17,1)
                const float* __restrict__ bias,     // (N,1)
                const float* __restrict__ attrs,    // (T,P,15)
                const int*   __restrict__ parents,  // (T,P)
                int N)
{
    __shared__ float stage[THREADS * 15];           // 15 KB
    const int tree  = blockIdx.x >> 12;             // P/256 = 4096 chunks/tree
    const int chunk = (blockIdx.x & 4095) * THREADS;
    const size_t tb = (size_t)tree * P_NODES;

    const int n = tree % N;
    float wv[17];
    #pragma unroll
    for (int i = 0; i < 17; i++) wv[i] = __ldg(&weight[n * 17 + i]);
    const float bv = __ldg(&bias[n]);

    // Stage 256 nodes x 15 attrs with vectorized coalesced loads (960 float4s).
    const float4* ap4 = (const float4*)(attrs + (tb + (size_t)chunk) * 15);
    float4* st4 = (float4*)stage;
    #pragma unroll
    for (int k = 0; k < 4; k++) {
        const int idx = k * THREADS + threadIdx.x;
        if (idx < (THREADS * 15) / 4) st4[idx] = __ldg(&ap4[idx]);
    }
    __syncthreads();

    const float* a = &stage[threadIdx.x * 15];      // stride 15: conflict-free
    float lin = bv;
    lin += a[0]*wv[0] + a[1]*wv[1] + a[2]*wv[2] + a[3]*wv[3] + a[4]*wv[4];
    #pragma unroll
    for (int c = 0; c < 9; c++)
        lin += __logf(fabsf(a[6 + c]) + EPS) * wv[5 + c];
    lin += __fdividef(__fsqrt_rn(a[7]), __fsqrt_rn(a[6]) + EPS) * wv[14];
    float sa, ca;
    __sincosf(a[5], &sa, &ca);
    lin += ca * wv[15] + sa * wv[16];
    const float score = __fdividef(1.0f, 1.0f + __expf(-lin));

    const int   node = chunk + threadIdx.x;
    const int   p    = __ldg(&parents[tb + node]);
    const float xv   = __ldg(&x[tb + node]);
    const float diff = (p == node) ? xv : (xv - __ldg(&x[tb + p]));

    g_rec[tb + node] = make_uint2(__float_as_uint(diff * score), (unsigned)p);
}

// ---------------------------------------------------------------------------
// K2: resolve nodes [0, T0) per tree via pointer doubling in shared memory.
// One block per tree. Sentinel at index T0 (value 0, self-parent).
// ---------------------------------------------------------------------------
__global__ __launch_bounds__(1024)
void k2_base(float* __restrict__ out)
{
    __shared__ float v0[T0 + 1], v1[T0 + 1];
    __shared__ int   p0[T0 + 1], p1[T0 + 1];

    const size_t tb = (size_t)blockIdx.x * P_NODES;

    for (int i = threadIdx.x; i <= T0; i += 1024) {
        if (i < T0) {
            const uint2 r = g_rec[tb + i];
            v0[i] = __uint_as_float(r.x);
            p0[i] = (i == 0 || (int)r.y == i) ? T0 : (int)r.y;  // root -> sentinel
        } else {
            v0[i] = 0.0f;
            p0[i] = T0;
        }
    }
    __syncthreads();

    float* cv = v0; float* nv = v1;
    int*   cp = p0; int*   np = p1;
    #pragma unroll 1
    for (int it = 0; it < 11; it++) {               // 2^11 >= T0 covers any depth
        for (int i = threadIdx.x; i <= T0; i += 1024) {
            const int pp = cp[i];
            nv[i] = cv[i] + cv[pp];
            np[i] = cp[pp];
        }
        __syncthreads();
        float* tv = cv; cv = nv; nv = tv;
        int*   tp = cp; cp = np; np = tp;
    }

    for (int i = threadIdx.x; i < T0; i += 1024)
        out[tb + i] = cv[i];
}

// ---------------------------------------------------------------------------
// K3/K4: each thread walks its node's ancestor chain (records are immutable),
// summing contribs, until the index drops below LOW; then adds the already-
// resolved out[ancestor]. Deterministic order, no synchronization.
// ---------------------------------------------------------------------------
template <int LOW, int BASE>
__global__ __launch_bounds__(THREADS)
void k_walk(float* __restrict__ out, int blocks_per_tree)
{
    const int tree = blockIdx.x / blocks_per_tree;
    const int lb   = blockIdx.x - tree * blocks_per_tree;
    const size_t tb = (size_t)tree * P_NODES;
    const int node = BASE + lb * THREADS + threadIdx.x;

    uint2 r = __ldg(&g_rec[tb + node]);
    float sum = __uint_as_float(r.x);
    unsigned q = r.y;
    #pragma unroll 1
    while (q >= (unsigned)LOW) {
        r = __ldg(&g_rec[tb + q]);
        sum += __uint_as_float(r.x);
        q = r.y;
    }
    sum += __ldg(&out[tb + q]);                     // resolved by earlier kernel
    out[tb + node] = sum;
}

// ---------------------------------------------------------------------------
extern "C" void kernel_launch(void* const* d_in, const int* in_sizes, int n_in,
                              void* d_out, int out_size)
{
    const float* x       = (const float*)d_in[0];   // (B,N,H,W) f32
    const float* weight  = (const float*)d_in[1];   // (N,17,1)  f32
    const float* bias    = (const float*)d_in[2];   // (N,1)     f32
    const float* attrs   = (const float*)d_in[3];   // (B,N,P,15) f32
    const int*   parents = (const int*)d_in[4];     // (B,N,P)   i32
    float* out = (float*)d_out;

    const int n_trees = in_sizes[0] / (int)P_NODES; // B*N = 4
    const int N       = in_sizes[1] / 17;

    // K1: full streaming pass
    k1_contrib<<<n_trees * (P_NODES / THREADS), THREADS>>>(x, weight, bias, attrs, parents, N);
    // K2: base tier via in-block pointer doubling
    k2_base<<<n_trees, 1024>>>(out);
    // K3: [T0, T1) walk to < T0
    {
        const int bpt = (T1 - T0) / THREADS;        // 504
        k_walk<T0, T0><<<n_trees * bpt, THREADS>>>(out, bpt);
    }
    // K4: [T1, P) walk to < T1
    {
        const int bpt = ((int)P_NODES - T1) / THREADS; // 3584
        k_walk<T1, T1><<<n_trees * bpt, THREADS>>>(out, bpt);
    }
}